// round 11
// baseline (speedup 1.0000x reference)
#include <cuda_runtime.h>
#include <cuda_bf16.h>

typedef unsigned long long u64;

#define T_LEN  128
#define H3     60
#define HID    20
#define LOUT   15
#define NB     2048

__device__ __forceinline__ u64 fma2(u64 a, u64 b, u64 c){
  u64 d; asm("fma.rn.f32x2 %0, %1, %2, %3;" : "=l"(d) : "l"(a), "l"(b), "l"(c)); return d;
}
__device__ __forceinline__ u64 pack2(float x, float y){
  u64 d; asm("mov.b64 %0, {%1, %2};" : "=l"(d) : "f"(x), "f"(y)); return d;
}
__device__ __forceinline__ float2 unpk(u64 v){
  float2 f; asm("mov.b64 {%0, %1}, %2;" : "=f"(f.x), "=f"(f.y) : "l"(v)); return f;
}
__device__ __forceinline__ float tanh_ap(float x){
  float y; asm("tanh.approx.f32 %0, %1;" : "=f"(y) : "f"(x)); return y;
}
__device__ __forceinline__ float sig_ap(float x){
  return fmaf(0.5f, tanh_ap(0.5f * x), 0.5f);
}

__global__ void __launch_bounds__(32) gru2_kernel(
    const int*   __restrict__ x,
    const float* __restrict__ W0,
    const float* __restrict__ U0,  const float* __restrict__ b0i, const float* __restrict__ b0r,
    const float* __restrict__ W1,  const float* __restrict__ U1,
    const float* __restrict__ b1i, const float* __restrict__ b1r,
    const float* __restrict__ Wd,  const float* __restrict__ bd,
    float* __restrict__ out)
{
  const int t  = threadIdx.x;
  const int b  = blockIdx.x;
  const int tl = (t < 30) ? t : 0;
  // column ownership: lane u<20 owns z-col u and r-col 20+u (gate preacts lane-local);
  // lane 20+a owns xh-cols 40+2a, 41+2a (exported to nonlin lanes via shfl)
  const int c0   = (tl < 20) ? tl : 40 + 2 * (tl - 20);
  const int c1   = (tl < 20) ? 20 + tl : c0 + 1;
  const int hsrc = 20 + (tl >> 1);      // h-lane holding xh/rh for unit tl
  const int odd  = tl & 1;

  // hidden states: plain 20-float arrays (K-packed pairs read as ulonglong2)
  __shared__ __align__(16) float hs0[20];
  __shared__ __align__(16) float hs1[20];
  __shared__ int xs[T_LEN];

  // ---- weights K-packed per owned column: wp[col_slot][i] = {W[2i,c],W[2i+1,c]} ----
  u64 u0p[2][10], w1p[2][10], u1p[2][10];
#pragma unroll
  for (int i = 0; i < 10; i++){
    u0p[0][i] = pack2(U0[(2*i) * H3 + c0], U0[(2*i + 1) * H3 + c0]);
    u0p[1][i] = pack2(U0[(2*i) * H3 + c1], U0[(2*i + 1) * H3 + c1]);
    w1p[0][i] = pack2(W1[(2*i) * H3 + c0], W1[(2*i + 1) * H3 + c0]);
    w1p[1][i] = pack2(W1[(2*i) * H3 + c1], W1[(2*i + 1) * H3 + c1]);
    u1p[0][i] = pack2(U1[(2*i) * H3 + c0], U1[(2*i + 1) * H3 + c0]);
    u1p[1][i] = pack2(U1[(2*i) * H3 + c1], U1[(2*i + 1) * H3 + c1]);
  }
  const float bi0_0 = b0i[c0], bi0_1 = b0i[c1];
  const float br0_0 = b0r[c0], br0_1 = b0r[c1];
  const float bi1_0 = b1i[c0], bi1_1 = b1i[c1];
  const float br1_0 = b1r[c0], br1_1 = b1r[c1];

#pragma unroll
  for (int i = t; i < 20; i += 32){ hs0[i] = 0.f; hs1[i] = 0.f; }
#pragma unroll 4
  for (int i = t; i < T_LEN; i += 32) xs[i] = x[(long)b * T_LEN + i];
  __syncwarp();

  float hp0 = 0.f, hp1 = 0.f;   // lane u<20 keeps h_u per layer

  // register-carried h0 K-pairs: h0c[i] = {h0_2i, h0_2i+1}
  u64 h0c[10];
#pragma unroll
  for (int i = 0; i < 10; i++) h0c[i] = 0ull;

  // W0 gather for owned columns (+ b0i), prefetched one step ahead
  int row = xs[0] * H3;
  float g0 = W0[row + c0] + bi0_0;
  float g1 = W0[row + c1] + bi0_1;

  for (int step = 0; step < T_LEN; step++){
    const int nt  = (step + 1 < T_LEN) ? step + 1 : step;
    const int nr  = xs[nt] * H3;
    const float ng0 = W0[nr + c0] + bi0_0;
    const float ng1 = W0[nr + c1] + bi0_1;

    // ===== layer 0: matvec on carried h0 (zero loads) + nonlinearity =====
    {
      u64 a0 = 0ull, a1 = 0ull;
#pragma unroll
      for (int i = 0; i < 10; i++){
        a0 = fma2(u0p[0][i], h0c[i], a0);
        a1 = fma2(u0p[1][i], h0c[i], a1);
      }
      const float2 f0 = unpk(a0), f1 = unpk(a1);
      const float e0 = f0.x + f0.y + br0_0;     // rec preact, col c0
      const float e1 = f1.x + f1.y + br0_1;     // rec preact, col c1
      const u64 xq = __shfl_sync(0xffffffffu, pack2(g0, g1), hsrc);
      const u64 rq = __shfl_sync(0xffffffffu, pack2(e0, e1), hsrc);
      const float z = sig_ap(g0 + e0);          // lane-local z (col u)
      const float r = sig_ap(g1 + e1);          // lane-local r (col 20+u)
      const float2 xf = unpk(xq), rf = unpk(rq);
      const float xh = odd ? xf.y : xf.x;
      const float rh = odd ? rf.y : rf.x;
      const float hh = tanh_ap(fmaf(r, rh, xh));
      const float hn = fmaf(z, hp0 - hh, hh);
      hp0 = hn;
      if (t < HID) hs0[t] = hn;
    }
    __syncwarp();

    // ===== layer 1 matvec: fresh h0 (doubles as next-step carry) + old h1 =====
    float ga, gb, ea, eb;
    {
      const ulonglong2* p0 = (const ulonglong2*)hs0;
      const ulonglong2* p1 = (const ulonglong2*)hs1;
      u64 a0 = 0ull, a1 = 0ull, r0 = 0ull, r1 = 0ull;
#pragma unroll
      for (int i = 0; i < 5; i++){
        const ulonglong2 q0 = p0[i];
        const ulonglong2 q1 = p1[i];
        h0c[2*i]     = q0.x;                  // carry for next step's MV0
        h0c[2*i + 1] = q0.y;
        a0 = fma2(w1p[0][2*i], q0.x, a0);  a0 = fma2(w1p[0][2*i + 1], q0.y, a0);
        a1 = fma2(w1p[1][2*i], q0.x, a1);  a1 = fma2(w1p[1][2*i + 1], q0.y, a1);
        r0 = fma2(u1p[0][2*i], q1.x, r0);  r0 = fma2(u1p[0][2*i + 1], q1.y, r0);
        r1 = fma2(u1p[1][2*i], q1.x, r1);  r1 = fma2(u1p[1][2*i + 1], q1.y, r1);
      }
      const float2 fa0 = unpk(a0), fa1 = unpk(a1), fr0 = unpk(r0), fr1 = unpk(r1);
      ga = fa0.x + fa0.y + bi1_0;               // input-path preact, col c0
      gb = fa1.x + fa1.y + bi1_1;               // input-path preact, col c1
      ea = fr0.x + fr0.y + br1_0;               // rec-path preact, col c0
      eb = fr1.x + fr1.y + br1_1;               // rec-path preact, col c1
    }
    __syncwarp();   // all hs1 reads complete before NL1 overwrites

    // ===== layer 1 nonlinearity =====
    {
      const u64 xq = __shfl_sync(0xffffffffu, pack2(ga, gb), hsrc);
      const u64 rq = __shfl_sync(0xffffffffu, pack2(ea, eb), hsrc);
      const float z = sig_ap(ga + ea);
      const float r = sig_ap(gb + eb);
      const float2 xf = unpk(xq), rf = unpk(rq);
      const float xh = odd ? xf.y : xf.x;
      const float rh = odd ? rf.y : rf.x;
      const float hh = tanh_ap(fmaf(r, rh, xh));
      const float hn = fmaf(z, hp1 - hh, hh);
      hp1 = hn;
      if (t < HID) hs1[t] = hn;
    }
    __syncwarp();   // NL1 store visible before next step's MV1 loads

    g0 = ng0; g1 = ng1;
  }

  // ===== epilogue: softmax(h1 @ Wd + bd) =====
  {
    float val = -1e30f;
    if (t < LOUT){
      float acc = bd[t];
#pragma unroll
      for (int k = 0; k < HID; k++)
        acc = fmaf(hs1[k], Wd[k * LOUT + t], acc);
      val = acc;
    }
    float m = val;
#pragma unroll
    for (int off = 16; off > 0; off >>= 1)
      m = fmaxf(m, __shfl_xor_sync(0xffffffffu, m, off));
    const float e = (t < LOUT) ? __expf(val - m) : 0.f;
    float s = e;
#pragma unroll
    for (int off = 16; off > 0; off >>= 1)
      s += __shfl_xor_sync(0xffffffffu, s, off);
    if (t < LOUT)
      out[(long)b * LOUT + t] = __fdividef(e, s);
  }
}

extern "C" void kernel_launch(void* const* d_in, const int* in_sizes, int n_in,
                              void* d_out, int out_size)
{
  const int*   x   = (const int*)  d_in[0];
  const float* W0  = (const float*)d_in[1];
  const float* U0  = (const float*)d_in[2];
  const float* b0i = (const float*)d_in[3];
  const float* b0r = (const float*)d_in[4];
  const float* W1  = (const float*)d_in[5];
  const float* U1  = (const float*)d_in[6];
  const float* b1i = (const float*)d_in[7];
  const float* b1r = (const float*)d_in[8];
  const float* Wd  = (const float*)d_in[9];
  const float* bd  = (const float*)d_in[10];
  // d_in[11] = drop_rate (identity, ignored)
  float* out = (float*)d_out;

  gru2_kernel<<<NB, 32>>>(x, W0, U0, b0i, b0r, W1, U1, b1i, b1r, Wd, bd, out);
}

// round 12
// speedup vs baseline: 1.0280x; 1.0280x over previous
#include <cuda_runtime.h>
#include <cuda_bf16.h>

typedef unsigned long long u64;

#define T_LEN  128
#define H3     60
#define HID    20
#define LOUT   15
#define NB     2048

__device__ __forceinline__ u64 fma2(u64 a, u64 b, u64 c){
  u64 d; asm("fma.rn.f32x2 %0, %1, %2, %3;" : "=l"(d) : "l"(a), "l"(b), "l"(c)); return d;
}
__device__ __forceinline__ u64 pack2(float x, float y){
  u64 d; asm("mov.b64 %0, {%1, %2};" : "=l"(d) : "f"(x), "f"(y)); return d;
}
__device__ __forceinline__ float2 unpk(u64 v){
  float2 f; asm("mov.b64 {%0, %1}, %2;" : "=f"(f.x), "=f"(f.y) : "l"(v)); return f;
}
__device__ __forceinline__ float tanh_ap(float x){
  float y; asm("tanh.approx.f32 %0, %1;" : "=f"(y) : "f"(x)); return y;
}
__device__ __forceinline__ float sig_ap(float x){
  return fmaf(0.5f, tanh_ap(0.5f * x), 0.5f);
}

__global__ void __launch_bounds__(32) gru2_kernel(
    const int*   __restrict__ x,
    const float* __restrict__ W0,
    const float* __restrict__ U0,  const float* __restrict__ b0i, const float* __restrict__ b0r,
    const float* __restrict__ W1,  const float* __restrict__ U1,
    const float* __restrict__ b1i, const float* __restrict__ b1r,
    const float* __restrict__ Wd,  const float* __restrict__ bd,
    float* __restrict__ out)
{
  const int t     = threadIdx.x;
  const int bbase = blockIdx.x * 2;
  const int tl    = (t < 30) ? t : 0;
  // column ownership: lane u<20 owns z-col u and r-col 20+u (gate preacts lane-local);
  // lane 20+a owns xh-cols 40+2a, 41+2a (exported to nonlin lanes via shfl)
  const int c0   = (tl < 20) ? tl : 40 + 2 * (tl - 20);
  const int c1   = (tl < 20) ? 20 + tl : c0 + 1;
  const int hsrc = 20 + (tl >> 1);      // h-lane holding xh/rh for unit tl
  const int odd  = tl & 1;

  __shared__ __align__(16) float hs0[2][20];
  __shared__ __align__(16) float hs1[2][20];
  __shared__ int xs[2][T_LEN];

  // ---- weights K-packed per owned column: wp[col_slot][i] = {W[2i,c],W[2i+1,c]} ----
  u64 u0p[2][10], w1p[2][10], u1p[2][10];
#pragma unroll
  for (int i = 0; i < 10; i++){
    u0p[0][i] = pack2(U0[(2*i) * H3 + c0], U0[(2*i + 1) * H3 + c0]);
    u0p[1][i] = pack2(U0[(2*i) * H3 + c1], U0[(2*i + 1) * H3 + c1]);
    w1p[0][i] = pack2(W1[(2*i) * H3 + c0], W1[(2*i + 1) * H3 + c0]);
    w1p[1][i] = pack2(W1[(2*i) * H3 + c1], W1[(2*i + 1) * H3 + c1]);
    u1p[0][i] = pack2(U1[(2*i) * H3 + c0], U1[(2*i + 1) * H3 + c0]);
    u1p[1][i] = pack2(U1[(2*i) * H3 + c1], U1[(2*i + 1) * H3 + c1]);
  }
  const float bi0_0 = b0i[c0], bi0_1 = b0i[c1];
  const float br0_0 = b0r[c0], br0_1 = b0r[c1];
  const float bi1_0 = b1i[c0], bi1_1 = b1i[c1];
  const float br1_0 = b1r[c0], br1_1 = b1r[c1];

#pragma unroll
  for (int i = t; i < 40; i += 32){ ((float*)hs0)[i] = 0.f; ((float*)hs1)[i] = 0.f; }
#pragma unroll 4
  for (int i = t; i < T_LEN; i += 32){
    xs[0][i] = x[(long)bbase * T_LEN + i];
    xs[1][i] = x[(long)(bbase + 1) * T_LEN + i];
  }
  __syncwarp();

  float hp0[2] = {0.f, 0.f};
  float hp1[2] = {0.f, 0.f};

  // register-carried h0 K-pairs: h0c[be][i] = {h0_2i, h0_2i+1}
  u64 h0c[2][10];
#pragma unroll
  for (int be = 0; be < 2; be++)
#pragma unroll
    for (int i = 0; i < 10; i++) h0c[be][i] = 0ull;

  // embedding gather for step 0 (owned columns + b0i)
  float g0[2], g1[2];
#pragma unroll
  for (int be = 0; be < 2; be++){
    const int row = xs[be][0] * H3;
    g0[be] = W0[row + c0] + bi0_0;
    g1[be] = W0[row + c1] + bi0_1;
  }

  // ---- prologue: MV0 for step 0 (h0c = 0 → rec preact = bias) ----
  float e0[2], e1[2];
#pragma unroll
  for (int be = 0; be < 2; be++){
    u64 a0 = 0ull, a1 = 0ull;
#pragma unroll
    for (int i = 0; i < 10; i++){
      a0 = fma2(u0p[0][i], h0c[be][i], a0);
      a1 = fma2(u0p[1][i], h0c[be][i], a1);
    }
    const float2 f0 = unpk(a0), f1 = unpk(a1);
    e0[be] = f0.x + f0.y + br0_0;
    e1[be] = f1.x + f1.y + br0_1;
  }

  for (int step = 0; step < T_LEN; step++){
    const int nt = (step + 1 < T_LEN) ? step + 1 : step;
    float ng0[2], ng1[2];
#pragma unroll
    for (int be = 0; be < 2; be++){
      const int nrow = xs[be][nt] * H3;
      ng0[be] = W0[nrow + c0] + bi0_0;
      ng1[be] = W0[nrow + c1] + bi0_1;
    }

    // ===== NL0_t: consume MV0_t preacts (e0,e1) =====
#pragma unroll
    for (int be = 0; be < 2; be++){
      const u64 xq = __shfl_sync(0xffffffffu, pack2(g0[be], g1[be]), hsrc);
      const u64 rq = __shfl_sync(0xffffffffu, pack2(e0[be], e1[be]), hsrc);
      const float z = sig_ap(g0[be] + e0[be]);
      const float r = sig_ap(g1[be] + e1[be]);
      const float2 xf = unpk(xq), rf = unpk(rq);
      const float xh = odd ? xf.y : xf.x;
      const float rh = odd ? rf.y : rf.x;
      const float hh = tanh_ap(fmaf(r, rh, xh));
      const float hn = fmaf(z, hp0[be] - hh, hh);
      hp0[be] = hn;
      if (t < HID) hs0[be][t] = hn;
    }
    __syncwarp();    // hs0 stores visible; also protects last iter's hs1 store

    // ===== MV1_t: fresh h0 (doubles as carry) + old h1 =====
    float ga[2], gb[2], ea[2], eb[2];
#pragma unroll
    for (int be = 0; be < 2; be++){
      const ulonglong2* p0 = (const ulonglong2*)hs0[be];
      const ulonglong2* p1 = (const ulonglong2*)hs1[be];
      u64 a0 = 0ull, a1 = 0ull, r0 = 0ull, r1 = 0ull;
#pragma unroll
      for (int i = 0; i < 5; i++){
        const ulonglong2 q0 = p0[i];
        const ulonglong2 q1 = p1[i];
        h0c[be][2*i]     = q0.x;
        h0c[be][2*i + 1] = q0.y;
        a0 = fma2(w1p[0][2*i], q0.x, a0);  a0 = fma2(w1p[0][2*i + 1], q0.y, a0);
        a1 = fma2(w1p[1][2*i], q0.x, a1);  a1 = fma2(w1p[1][2*i + 1], q0.y, a1);
        r0 = fma2(u1p[0][2*i], q1.x, r0);  r0 = fma2(u1p[0][2*i + 1], q1.y, r0);
        r1 = fma2(u1p[1][2*i], q1.x, r1);  r1 = fma2(u1p[1][2*i + 1], q1.y, r1);
      }
      const float2 fa0 = unpk(a0), fa1 = unpk(a1), fr0 = unpk(r0), fr1 = unpk(r1);
      ga[be] = fa0.x + fa0.y + bi1_0;
      gb[be] = fa1.x + fa1.y + bi1_1;
      ea[be] = fr0.x + fr0.y + br1_0;
      eb[be] = fr1.x + fr1.y + br1_1;
    }

    // ===== MV0_{t+1}: pure register compute, overlaps NL1_t's latency =====
#pragma unroll
    for (int be = 0; be < 2; be++){
      u64 a0 = 0ull, a1 = 0ull;
#pragma unroll
      for (int i = 0; i < 10; i++){
        a0 = fma2(u0p[0][i], h0c[be][i], a0);
        a1 = fma2(u0p[1][i], h0c[be][i], a1);
      }
      const float2 f0 = unpk(a0), f1 = unpk(a1);
      e0[be] = f0.x + f0.y + br0_0;
      e1[be] = f1.x + f1.y + br0_1;
    }
    __syncwarp();    // hs1 reads (MV1) complete before NL1 overwrites

    // ===== NL1_t =====
#pragma unroll
    for (int be = 0; be < 2; be++){
      const u64 xq = __shfl_sync(0xffffffffu, pack2(ga[be], gb[be]), hsrc);
      const u64 rq = __shfl_sync(0xffffffffu, pack2(ea[be], eb[be]), hsrc);
      const float z = sig_ap(ga[be] + ea[be]);
      const float r = sig_ap(gb[be] + eb[be]);
      const float2 xf = unpk(xq), rf = unpk(rq);
      const float xh = odd ? xf.y : xf.x;
      const float rh = odd ? rf.y : rf.x;
      const float hh = tanh_ap(fmaf(r, rh, xh));
      const float hn = fmaf(z, hp1[be] - hh, hh);
      hp1[be] = hn;
      if (t < HID) hs1[be][t] = hn;
    }
    // NL1's hs1 store is protected by the first syncwarp of the next iteration

#pragma unroll
    for (int be = 0; be < 2; be++){ g0[be] = ng0[be]; g1[be] = ng1[be]; }
  }

  // ===== epilogue: softmax(h1 @ Wd + bd) =====
  __syncwarp();
#pragma unroll
  for (int be = 0; be < 2; be++){
    float val = -1e30f;
    if (t < LOUT){
      float acc = bd[t];
#pragma unroll
      for (int k = 0; k < HID; k++)
        acc = fmaf(hs1[be][k], Wd[k * LOUT + t], acc);
      val = acc;
    }
    float m = val;
#pragma unroll
    for (int off = 16; off > 0; off >>= 1)
      m = fmaxf(m, __shfl_xor_sync(0xffffffffu, m, off));
    const float e = (t < LOUT) ? __expf(val - m) : 0.f;
    float s = e;
#pragma unroll
    for (int off = 16; off > 0; off >>= 1)
      s += __shfl_xor_sync(0xffffffffu, s, off);
    if (t < LOUT)
      out[(long)(bbase + be) * LOUT + t] = __fdividef(e, s);
  }
}

extern "C" void kernel_launch(void* const* d_in, const int* in_sizes, int n_in,
                              void* d_out, int out_size)
{
  const int*   x   = (const int*)  d_in[0];
  const float* W0  = (const float*)d_in[1];
  const float* U0  = (const float*)d_in[2];
  const float* b0i = (const float*)d_in[3];
  const float* b0r = (const float*)d_in[4];
  const float* W1  = (const float*)d_in[5];
  const float* U1  = (const float*)d_in[6];
  const float* b1i = (const float*)d_in[7];
  const float* b1r = (const float*)d_in[8];
  const float* Wd  = (const float*)d_in[9];
  const float* bd  = (const float*)d_in[10];
  // d_in[11] = drop_rate (identity, ignored)
  float* out = (float*)d_out;

  gru2_kernel<<<NB / 2, 32>>>(x, W0, U0, b0i, b0r, W1, U1, b1i, b1r, Wd, bd, out);
}

// round 13
// speedup vs baseline: 1.0782x; 1.0489x over previous
#include <cuda_runtime.h>
#include <cuda_bf16.h>

typedef unsigned long long u64;

#define T_LEN  128
#define H3     60
#define HID    20
#define LOUT   15
#define NB     2048

__device__ __forceinline__ u64 fma2(u64 a, u64 b, u64 c){
  u64 d; asm("fma.rn.f32x2 %0, %1, %2, %3;" : "=l"(d) : "l"(a), "l"(b), "l"(c)); return d;
}
__device__ __forceinline__ u64 add2(u64 a, u64 b){
  u64 d; asm("add.rn.f32x2 %0, %1, %2;" : "=l"(d) : "l"(a), "l"(b)); return d;
}
__device__ __forceinline__ u64 pack2(float x, float y){
  u64 d; asm("mov.b64 %0, {%1, %2};" : "=l"(d) : "f"(x), "f"(y)); return d;
}
__device__ __forceinline__ float2 unpk(u64 v){
  float2 f; asm("mov.b64 {%0, %1}, %2;" : "=f"(f.x), "=f"(f.y) : "l"(v)); return f;
}
__device__ __forceinline__ float tanh_ap(float x){
  float y; asm("tanh.approx.f32 %0, %1;" : "=f"(y) : "f"(x)); return y;
}
__device__ __forceinline__ float sig_ap(float x){
  return fmaf(0.5f, tanh_ap(0.5f * x), 0.5f);
}

__global__ void __launch_bounds__(32) gru2_kernel(
    const int*   __restrict__ x,
    const float* __restrict__ W0,
    const float* __restrict__ U0,  const float* __restrict__ b0i, const float* __restrict__ b0r,
    const float* __restrict__ W1,  const float* __restrict__ U1,
    const float* __restrict__ b1i, const float* __restrict__ b1r,
    const float* __restrict__ Wd,  const float* __restrict__ bd,
    float* __restrict__ out)
{
  const int t     = threadIdx.x;
  const int bbase = blockIdx.x * 2;
  const int tl    = (t < 30) ? t : 0;
  // column ownership: lane u<20 owns z-col u and r-col 20+u (gate preacts lane-local);
  // lane 20+a owns xh-cols 40+2a, 41+2a (exported to nonlin lanes via shfl)
  const int c0   = (tl < 20) ? tl : 40 + 2 * (tl - 20);
  const int c1   = (tl < 20) ? 20 + tl : c0 + 1;
  const int hsrc = 20 + (tl >> 1);      // h-lane holding xh/rh for unit tl
  const int odd  = tl & 1;

  __shared__ __align__(16) float hs0[2][20];
  __shared__ __align__(16) float hs1[2][20];
  __shared__ int xs[2][T_LEN];

  // ---- weights K-packed per owned column: wp[col_slot][i] = {W[2i,c],W[2i+1,c]} ----
  u64 u0p[2][10], w1p[2][10], u1p[2][10];
#pragma unroll
  for (int i = 0; i < 10; i++){
    u0p[0][i] = pack2(U0[(2*i) * H3 + c0], U0[(2*i + 1) * H3 + c0]);
    u0p[1][i] = pack2(U0[(2*i) * H3 + c1], U0[(2*i + 1) * H3 + c1]);
    w1p[0][i] = pack2(W1[(2*i) * H3 + c0], W1[(2*i + 1) * H3 + c0]);
    w1p[1][i] = pack2(W1[(2*i) * H3 + c1], W1[(2*i + 1) * H3 + c1]);
    u1p[0][i] = pack2(U1[(2*i) * H3 + c0], U1[(2*i + 1) * H3 + c0]);
    u1p[1][i] = pack2(U1[(2*i) * H3 + c1], U1[(2*i + 1) * H3 + c1]);
  }
  const float bi0_0 = b0i[c0], bi0_1 = b0i[c1];
  const float br0_0 = b0r[c0], br0_1 = b0r[c1];
  const float bi1_0 = b1i[c0], bi1_1 = b1i[c1];
  const float br1_0 = b1r[c0], br1_1 = b1r[c1];

#pragma unroll
  for (int i = t; i < 40; i += 32){ ((float*)hs0)[i] = 0.f; ((float*)hs1)[i] = 0.f; }
#pragma unroll 4
  for (int i = t; i < T_LEN; i += 32){
    xs[0][i] = x[(long)bbase * T_LEN + i];
    xs[1][i] = x[(long)(bbase + 1) * T_LEN + i];
  }
  __syncwarp();

  float hp0[2] = {0.f, 0.f};
  float hp1[2] = {0.f, 0.f};

  // register-carried h0 K-pairs: h0c[be][i] = {h0_2i, h0_2i+1}
  u64 h0c[2][10];
#pragma unroll
  for (int be = 0; be < 2; be++)
#pragma unroll
    for (int i = 0; i < 10; i++) h0c[be][i] = 0ull;

  // embedding gather for step 0 (owned columns + b0i)
  float g0[2], g1[2];
#pragma unroll
  for (int be = 0; be < 2; be++){
    const int row = xs[be][0] * H3;
    g0[be] = W0[row + c0] + bi0_0;
    g1[be] = W0[row + c1] + bi0_1;
  }

  for (int step = 0; step < T_LEN; step++){
    const int nt = (step + 1 < T_LEN) ? step + 1 : step;
    float ng0[2], ng1[2];
#pragma unroll
    for (int be = 0; be < 2; be++){
      const int nrow = xs[be][nt] * H3;
      ng0[be] = W0[nrow + c0] + bi0_0;
      ng1[be] = W0[nrow + c1] + bi0_1;
    }

    // ===== MV0_t + NL0_t: matvec on carried h0 (zero loads), split 5-deep chains =====
#pragma unroll
    for (int be = 0; be < 2; be++){
      u64 a0 = 0ull, a0b = 0ull, a1 = 0ull, a1b = 0ull;
#pragma unroll
      for (int i = 0; i < 5; i++){
        a0  = fma2(u0p[0][i],     h0c[be][i],     a0);
        a0b = fma2(u0p[0][i + 5], h0c[be][i + 5], a0b);
        a1  = fma2(u0p[1][i],     h0c[be][i],     a1);
        a1b = fma2(u0p[1][i + 5], h0c[be][i + 5], a1b);
      }
      const float2 f0 = unpk(add2(a0, a0b));
      const float2 f1 = unpk(add2(a1, a1b));
      const float e0 = f0.x + f0.y + br0_0;     // rec preact, col c0
      const float e1 = f1.x + f1.y + br0_1;     // rec preact, col c1
      const u64 xq = __shfl_sync(0xffffffffu, pack2(g0[be], g1[be]), hsrc);
      const u64 rq = __shfl_sync(0xffffffffu, pack2(e0, e1), hsrc);
      const float z = sig_ap(g0[be] + e0);
      const float r = sig_ap(g1[be] + e1);
      const float2 xf = unpk(xq), rf = unpk(rq);
      const float xh = odd ? xf.y : xf.x;
      const float rh = odd ? rf.y : rf.x;
      const float hh = tanh_ap(fmaf(r, rh, xh));
      const float hn = fmaf(z, hp0[be] - hh, hh);
      hp0[be] = hn;
      if (t < HID) hs0[be][t] = hn;
    }
    __syncwarp();   // A: hs0 stores -> MV1 reads; also orders prev NL1's hs1 store

    // ===== MV1_t: fresh h0 (doubles as next-step carry) + old h1, split chains =====
    float ga[2], gb[2], ea[2], eb[2];
#pragma unroll
    for (int be = 0; be < 2; be++){
      const ulonglong2* p0 = (const ulonglong2*)hs0[be];
      const ulonglong2* p1 = (const ulonglong2*)hs1[be];
      u64 a0x = 0ull, a0y = 0ull, a1x = 0ull, a1y = 0ull;
      u64 r0x = 0ull, r0y = 0ull, r1x = 0ull, r1y = 0ull;
#pragma unroll
      for (int i = 0; i < 5; i++){
        const ulonglong2 q0 = p0[i];
        const ulonglong2 q1 = p1[i];
        h0c[be][2*i]     = q0.x;              // carry for next step's MV0
        h0c[be][2*i + 1] = q0.y;
        a0x = fma2(w1p[0][2*i], q0.x, a0x);  a0y = fma2(w1p[0][2*i + 1], q0.y, a0y);
        a1x = fma2(w1p[1][2*i], q0.x, a1x);  a1y = fma2(w1p[1][2*i + 1], q0.y, a1y);
        r0x = fma2(u1p[0][2*i], q1.x, r0x);  r0y = fma2(u1p[0][2*i + 1], q1.y, r0y);
        r1x = fma2(u1p[1][2*i], q1.x, r1x);  r1y = fma2(u1p[1][2*i + 1], q1.y, r1y);
      }
      const float2 fa0 = unpk(add2(a0x, a0y));
      const float2 fa1 = unpk(add2(a1x, a1y));
      const float2 fr0 = unpk(add2(r0x, r0y));
      const float2 fr1 = unpk(add2(r1x, r1y));
      ga[be] = fa0.x + fa0.y + bi1_0;
      gb[be] = fa1.x + fa1.y + bi1_1;
      ea[be] = fr0.x + fr0.y + br1_0;
      eb[be] = fr1.x + fr1.y + br1_1;
    }
    __syncwarp();   // B: hs1/hs0 reads complete before NL1/next-NL0 overwrite

    // ===== NL1_t =====
#pragma unroll
    for (int be = 0; be < 2; be++){
      const u64 xq = __shfl_sync(0xffffffffu, pack2(ga[be], gb[be]), hsrc);
      const u64 rq = __shfl_sync(0xffffffffu, pack2(ea[be], eb[be]), hsrc);
      const float z = sig_ap(ga[be] + ea[be]);
      const float r = sig_ap(gb[be] + eb[be]);
      const float2 xf = unpk(xq), rf = unpk(rq);
      const float xh = odd ? xf.y : xf.x;
      const float rh = odd ? rf.y : rf.x;
      const float hh = tanh_ap(fmaf(r, rh, xh));
      const float hn = fmaf(z, hp1[be] - hh, hh);
      hp1[be] = hn;
      if (t < HID) hs1[be][t] = hn;
    }
    // NL1's hs1 store is ordered before next MV1's read by barrier A of next iter

    g0[0] = ng0[0]; g1[0] = ng1[0];
    g0[1] = ng0[1]; g1[1] = ng1[1];
  }

  // ===== epilogue: softmax(h1 @ Wd + bd) =====
  __syncwarp();
#pragma unroll
  for (int be = 0; be < 2; be++){
    float val = -1e30f;
    if (t < LOUT){
      float acc = bd[t];
#pragma unroll
      for (int k = 0; k < HID; k++)
        acc = fmaf(hs1[be][k], Wd[k * LOUT + t], acc);
      val = acc;
    }
    float m = val;
#pragma unroll
    for (int off = 16; off > 0; off >>= 1)
      m = fmaxf(m, __shfl_xor_sync(0xffffffffu, m, off));
    const float e = (t < LOUT) ? __expf(val - m) : 0.f;
    float s = e;
#pragma unroll
    for (int off = 16; off > 0; off >>= 1)
      s += __shfl_xor_sync(0xffffffffu, s, off);
    if (t < LOUT)
      out[(long)(bbase + be) * LOUT + t] = __fdividef(e, s);
  }
}

extern "C" void kernel_launch(void* const* d_in, const int* in_sizes, int n_in,
                              void* d_out, int out_size)
{
  const int*   x   = (const int*)  d_in[0];
  const float* W0  = (const float*)d_in[1];
  const float* U0  = (const float*)d_in[2];
  const float* b0i = (const float*)d_in[3];
  const float* b0r = (const float*)d_in[4];
  const float* W1  = (const float*)d_in[5];
  const float* U1  = (const float*)d_in[6];
  const float* b1i = (const float*)d_in[7];
  const float* b1r = (const float*)d_in[8];
  const float* Wd  = (const float*)d_in[9];
  const float* bd  = (const float*)d_in[10];
  // d_in[11] = drop_rate (identity, ignored)
  float* out = (float*)d_out;

  gru2_kernel<<<NB / 2, 32>>>(x, W0, U0, b0i, b0r, W1, U1, b1i, b1r, Wd, bd, out);
}